// round 12
// baseline (speedup 1.0000x reference)
#include <cuda_runtime.h>
#include <cuda_fp16.h>
#include <math.h>
#include <stdint.h>

// Problem dims (fixed by the reference)
#define BATCH 256
#define NPIX  196
#define CDIM  2048
#define ADIM  512
#define LDIM  512
#define MTOT  (BATCH * NPIX)   // 50176 = 392 * 128

// GEMM tiling (mma.sync m16n8k16, fp16 in / f32 accum, single pass)
#define BM 128
#define BN 128
#define BK 64
#define NBLK (ADIM / BN)       // 4
#define NITER (CDIM / BK)      // 32
#define WM 64
#define WN 64
#define NSTAGE 3
#define NTHREADS 128

// Scratch (device globals — no allocation allowed)
__device__ float g_att2[BATCH * ADIM];
__device__ float g_att_part[NBLK * MTOT];
__device__ float g_alpha[MTOT];
__device__ __half g_Wc_h[ADIM * CDIM];                 // fp16(Wc)
__device__ __half g_A_h[(size_t)MTOT * CDIM];          // fp16(conv_out)

// smem: row stride 144B (64 fp16 + 16B pad) — 16B-chunk stride 9 mod 8 = 1, conflict-free LDSM
#define ROWB 144
#define TILEB (128 * ROWB)     // 18432
#define SM_A(s) ((s) * (2 * TILEB) + 0)
#define SM_B(s) ((s) * (2 * TILEB) + TILEB)
#define SMEM_BYTES (NSTAGE * 2 * TILEB)   // 110592

__device__ __forceinline__ uint32_t smem_to_u32(const void* p) {
    uint32_t a;
    asm("{ .reg .u64 t; cvta.to.shared.u64 t, %1; cvt.u32.u64 %0, t; }" : "=r"(a) : "l"(p));
    return a;
}
__device__ __forceinline__ void ldsm4(uint32_t* r, uint32_t addr) {
    asm volatile("ldmatrix.sync.aligned.m8n8.x4.shared.b16 {%0,%1,%2,%3}, [%4];"
                 : "=r"(r[0]), "=r"(r[1]), "=r"(r[2]), "=r"(r[3]) : "r"(addr));
}
__device__ __forceinline__ void mma16816(float* c, const uint32_t* a, const uint32_t* b) {
    asm volatile("mma.sync.aligned.m16n8k16.row.col.f32.f16.f16.f32 "
                 "{%0,%1,%2,%3}, {%4,%5,%6,%7}, {%8,%9}, {%0,%1,%2,%3};"
                 : "+f"(c[0]), "+f"(c[1]), "+f"(c[2]), "+f"(c[3])
                 : "r"(a[0]), "r"(a[1]), "r"(a[2]), "r"(a[3]), "r"(b[0]), "r"(b[1]));
}
#define CP_ASYNC16(dst, src) \
    asm volatile("cp.async.cg.shared.global [%0], [%1], 16;" :: "r"(dst), "l"(src))
#define CP_COMMIT() asm volatile("cp.async.commit_group;" ::: "memory")
#define CP_WAIT1()  asm volatile("cp.async.wait_group 1;" ::: "memory")
#define CP_WAIT0()  asm volatile("cp.async.wait_group 0;" ::: "memory")

__device__ __forceinline__ uint32_t pack_h(__half a, __half b) {
    return (uint32_t)__half_as_ushort(a) | ((uint32_t)__half_as_ushort(b) << 16);
}

// ---------------------------------------------------------------------------
// K0a: convert Wc -> fp16
// ---------------------------------------------------------------------------
__global__ void convert_wc_kernel(const float* __restrict__ Wc) {
    const size_t i4 = (size_t)blockIdx.x * 256 + threadIdx.x;
    float4 v = reinterpret_cast<const float4*>(Wc)[i4];
    reinterpret_cast<uint2*>(g_Wc_h)[i4] =
        make_uint2(pack_h(__float2half(v.x), __float2half(v.y)),
                   pack_h(__float2half(v.z), __float2half(v.w)));
}

// ---------------------------------------------------------------------------
// K0b: convert conv_out -> fp16
// ---------------------------------------------------------------------------
__global__ void convert_a_kernel(const float* __restrict__ A) {
    const size_t i4 = (size_t)blockIdx.x * 256 + threadIdx.x;
    float4 v = reinterpret_cast<const float4*>(A)[i4];
    reinterpret_cast<uint2*>(g_A_h)[i4] =
        make_uint2(pack_h(__float2half(v.x), __float2half(v.y)),
                   pack_h(__float2half(v.z), __float2half(v.w)));
}

// ---------------------------------------------------------------------------
// K1: att2[b][a] = lstm[b] . Wl[a] + bl[a]
// ---------------------------------------------------------------------------
__global__ void att2_kernel(const float* __restrict__ lstm,
                            const float* __restrict__ Wl,
                            const float* __restrict__ bl,
                            float* __restrict__ att2) {
    __shared__ float h[8][LDIM];
    const int b0 = blockIdx.x * 8;
    const int a = threadIdx.x;
    #pragma unroll
    for (int i = 0; i < 8; i++) h[i][a] = lstm[(b0 + i) * LDIM + a];
    __syncthreads();
    const float4* w4 = reinterpret_cast<const float4*>(Wl + (size_t)a * LDIM);
    float acc[8] = {0.f, 0.f, 0.f, 0.f, 0.f, 0.f, 0.f, 0.f};
    #pragma unroll 4
    for (int l4 = 0; l4 < LDIM / 4; l4++) {
        float4 wv = w4[l4];
        int l = l4 * 4;
        #pragma unroll
        for (int i = 0; i < 8; i++) {
            acc[i] += h[i][l + 0] * wv.x;
            acc[i] += h[i][l + 1] * wv.y;
            acc[i] += h[i][l + 2] * wv.z;
            acc[i] += h[i][l + 3] * wv.w;
        }
    }
    const float bv = bl[a];
    #pragma unroll
    for (int i = 0; i < 8; i++) att2[(b0 + i) * ADIM + a] = acc[i] + bv;
}

// ---------------------------------------------------------------------------
// K2: fp16 single-pass score GEMM, BK=64, 3-stage cp.async, 2 CTAs/SM.
// Grid (4, 392): bn fast => 4 CTAs share one A tile via L2.
// 128 threads (4 warps 2x2), warp tile 64x64, fragment double-buffering.
// ---------------------------------------------------------------------------
__global__ void __launch_bounds__(NTHREADS, 2)
score_gemm_kernel(const float* __restrict__ bc,
                  const float* __restrict__ Wf,
                  const float* __restrict__ att2,   // B x 512
                  float* __restrict__ att_part)     // NBLK x M
{
    extern __shared__ char sm[];
    const uint32_t sb = smem_to_u32(sm);
    const int tid = threadIdx.x;
    const int lane = tid & 31;
    const int wid = tid >> 5;
    const int warp_m = wid >> 1;       // 0..1
    const int warp_n = wid & 1;        // 0..1
    const int bn = blockIdx.x;         // 0..3 (fast: A-tile L2 sharing)
    const int bm = blockIdx.y;         // 0..391

    // ldmatrix per-lane offsets (k-quarter kk adds kk*32 bytes)
    uint32_t aoff[4], boff[4];
    {
        const int ar = lane & 15, abyte = (lane >> 4) * 16;
        #pragma unroll
        for (int mb = 0; mb < 4; mb++)
            aoff[mb] = (uint32_t)((warp_m * WM + mb * 16 + ar) * ROWB + abyte);
        const int bnr = (lane & 7) + ((lane >> 4) << 3);
        const int bbyte = ((lane >> 3) & 1) * 16;
        #pragma unroll
        for (int g = 0; g < 4; g++)
            boff[g] = (uint32_t)((warp_n * WN + g * 16 + bnr) * ROWB + bbyte);
    }

    // cp.async: per stage A and B are each 128 rows x 8 chunks(16B) = 1024 chunks
    // -> 8 chunks per thread per matrix (128 threads)
    int c_row[8]; int c_q[8]; uint32_t c_soff[8];
    #pragma unroll
    for (int i = 0; i < 8; i++) {
        const int idx = tid + NTHREADS * i;
        c_row[i] = idx >> 3;
        c_q[i] = idx & 7;
        c_soff[i] = (uint32_t)(c_row[i] * ROWB + c_q[i] * 16);
    }

    float acc[4][8][4];
    #pragma unroll
    for (int mb = 0; mb < 4; mb++)
        #pragma unroll
        for (int nb = 0; nb < 8; nb++)
            #pragma unroll
            for (int j = 0; j < 4; j++) acc[mb][nb][j] = 0.f;

    auto issue = [&](int s) {
        const int buf = s % NSTAGE;
        const int k0 = s * BK;
        #pragma unroll
        for (int i = 0; i < 8; i++) {
            const size_t ag = (size_t)(bm * BM + c_row[i]) * CDIM + k0 + c_q[i] * 8;
            CP_ASYNC16(sb + SM_A(buf) + c_soff[i], (const char*)(g_A_h + ag));
        }
        #pragma unroll
        for (int i = 0; i < 8; i++) {
            const size_t bg = (size_t)(bn * BN + c_row[i]) * CDIM + k0 + c_q[i] * 8;
            CP_ASYNC16(sb + SM_B(buf) + c_soff[i], (const char*)(g_Wc_h + bg));
        }
        CP_COMMIT();
    };

    issue(0); issue(1);
    CP_WAIT1();            // stage 0 complete
    __syncthreads();

    #pragma unroll 1
    for (int it = 0; it < NITER; it++) {
        const int buf = it % NSTAGE;
        const bool more = (it + 2 < NITER);
        if (more) issue(it + 2);

        // fragment double-buffer: LDSM for kk+1 overlaps MMA for kk
        uint32_t af[2][4][4], bf[2][4][4];
        #pragma unroll
        for (int g = 0; g < 4; g++) ldsm4(bf[0][g], sb + SM_B(buf) + boff[g]);
        #pragma unroll
        for (int mb = 0; mb < 4; mb++) ldsm4(af[0][mb], sb + SM_A(buf) + aoff[mb]);
        #pragma unroll
        for (int kk = 0; kk < 4; kk++) {
            const int cur = kk & 1, nxt = cur ^ 1;
            if (kk < 3) {
                #pragma unroll
                for (int g = 0; g < 4; g++)
                    ldsm4(bf[nxt][g], sb + SM_B(buf) + boff[g] + (kk + 1) * 32);
                #pragma unroll
                for (int mb = 0; mb < 4; mb++)
                    ldsm4(af[nxt][mb], sb + SM_A(buf) + aoff[mb] + (kk + 1) * 32);
            }
            #pragma unroll
            for (int mb = 0; mb < 4; mb++)
                #pragma unroll
                for (int nb = 0; nb < 8; nb++)
                    mma16816(acc[mb][nb], af[cur][mb], &bf[cur][nb >> 1][(nb & 1) * 2]);
        }

        if (more) { CP_WAIT1(); } else { CP_WAIT0(); }
        __syncthreads();
    }

    // ---- epilogue: relu(C + bc + att2) . Wf reduced over n ----
    float wfv[16], bcv[16];
    const int ncol0 = bn * BN + warp_n * WN;
    #pragma unroll
    for (int nb = 0; nb < 8; nb++)
        #pragma unroll
        for (int jj = 0; jj < 2; jj++) {
            const int n = ncol0 + nb * 8 + 2 * (lane & 3) + jj;
            wfv[nb * 2 + jj] = Wf[n];
            bcv[nb * 2 + jj] = bc[n];
        }

    float* red = reinterpret_cast<float*>(sm);   // [2][128]
    #pragma unroll
    for (int mb = 0; mb < 4; mb++) {
        #pragma unroll
        for (int half = 0; half < 2; half++) {
            const int m_loc = warp_m * WM + mb * 16 + (lane >> 2) + half * 8;
            const int m = bm * BM + m_loc;
            const int b = m / NPIX;
            const float* a2 = att2 + (size_t)b * ADIM + ncol0;
            float s = 0.f;
            #pragma unroll
            for (int nb = 0; nb < 8; nb++)
                #pragma unroll
                for (int jj = 0; jj < 2; jj++) {
                    const int ci = half * 2 + jj;
                    const int nrel = nb * 8 + 2 * (lane & 3) + jj;
                    float v = acc[mb][nb][ci] + bcv[nb * 2 + jj] + a2[nrel];
                    s += fmaxf(v, 0.f) * wfv[nb * 2 + jj];
                }
            s += __shfl_xor_sync(0xFFFFFFFF, s, 1);
            s += __shfl_xor_sync(0xFFFFFFFF, s, 2);
            if ((lane & 3) == 0) red[warp_n * BM + m_loc] = s;
        }
    }
    __syncthreads();
    if (tid < BM) {
        float s = red[0 * BM + tid] + red[1 * BM + tid];
        att_part[(size_t)bn * MTOT + bm * BM + tid] = s;
    }
}

// ---------------------------------------------------------------------------
// K3: softmax over P=196 per batch row (4 partials).
// ---------------------------------------------------------------------------
__global__ void softmax_kernel(const float* __restrict__ att_part,
                               const float* __restrict__ bf,
                               float* __restrict__ alpha) {
    __shared__ float sv[256];
    const int b = blockIdx.x;
    const int tid = threadIdx.x;
    float val = 0.f;
    float v = -INFINITY;
    if (tid < NPIX) {
        const int m = b * NPIX + tid;
        val = bf[0] + att_part[0 * MTOT + m] + att_part[1 * MTOT + m]
            + att_part[2 * MTOT + m] + att_part[3 * MTOT + m];
        v = val;
    }
    sv[tid] = v;
    __syncthreads();
    #pragma unroll
    for (int s = 128; s > 0; s >>= 1) {
        if (tid < s) sv[tid] = fmaxf(sv[tid], sv[tid + s]);
        __syncthreads();
    }
    const float mx = sv[0];
    __syncthreads();
    const float e = (tid < NPIX) ? expf(val - mx) : 0.f;
    sv[tid] = e;
    __syncthreads();
    #pragma unroll
    for (int s = 128; s > 0; s >>= 1) {
        if (tid < s) sv[tid] = sv[tid] + sv[tid + s];
        __syncthreads();
    }
    const float sum = sv[0];
    if (tid < NPIX) alpha[b * NPIX + tid] = e / sum;
}

// ---------------------------------------------------------------------------
// K4: out[b][c] = sum_p conv[b][p][c] * alpha[b][p]  (float4, 2 chains)
// ---------------------------------------------------------------------------
__global__ void pool_kernel(const float* __restrict__ conv,
                            const float* __restrict__ alpha,
                            float* __restrict__ out) {
    __shared__ float al[NPIX];
    const int b = blockIdx.y;
    const int c4 = blockIdx.x * 256 + threadIdx.x;
    if (threadIdx.x < NPIX) al[threadIdx.x] = alpha[b * NPIX + threadIdx.x];
    __syncthreads();
    const float4* cp = reinterpret_cast<const float4*>(conv + (size_t)b * NPIX * CDIM) + c4;
    float4 a0 = make_float4(0.f, 0.f, 0.f, 0.f);
    float4 a1 = make_float4(0.f, 0.f, 0.f, 0.f);
    #pragma unroll 4
    for (int p = 0; p < NPIX; p += 2) {
        float4 v0 = cp[(size_t)p * (CDIM / 4)];
        float4 v1 = cp[(size_t)(p + 1) * (CDIM / 4)];
        float w0 = al[p], w1 = al[p + 1];
        a0.x += v0.x * w0; a0.y += v0.y * w0; a0.z += v0.z * w0; a0.w += v0.w * w0;
        a1.x += v1.x * w1; a1.y += v1.y * w1; a1.z += v1.z * w1; a1.w += v1.w * w1;
    }
    float4 r = make_float4(a0.x + a1.x, a0.y + a1.y, a0.z + a1.z, a0.w + a1.w);
    reinterpret_cast<float4*>(out)[(size_t)b * (CDIM / 4) + c4] = r;
}

// ---------------------------------------------------------------------------
extern "C" void kernel_launch(void* const* d_in, const int* in_sizes, int n_in,
                              void* d_out, int out_size) {
    const float* conv = (const float*)d_in[0];
    const float* lstm = (const float*)d_in[1];
    const float* Wc   = (const float*)d_in[2];
    const float* bc   = (const float*)d_in[3];
    const float* Wl   = (const float*)d_in[4];
    const float* bl   = (const float*)d_in[5];
    const float* Wf   = (const float*)d_in[6];
    const float* bf   = (const float*)d_in[7];
    float* out = (float*)d_out;

    float* att2;     cudaGetSymbolAddress((void**)&att2, g_att2);
    float* att_part; cudaGetSymbolAddress((void**)&att_part, g_att_part);
    float* alpha;    cudaGetSymbolAddress((void**)&alpha, g_alpha);

    cudaFuncSetAttribute(score_gemm_kernel,
                         cudaFuncAttributeMaxDynamicSharedMemorySize, SMEM_BYTES);

    convert_wc_kernel<<<(ADIM * CDIM / 4) / 256, 256>>>(Wc);
    convert_a_kernel<<<(int)(((size_t)MTOT * CDIM / 4) / 256), 256>>>(conv);
    att2_kernel<<<BATCH / 8, LDIM>>>(lstm, Wl, bl, att2);

    dim3 gg(NBLK, MTOT / BM);
    score_gemm_kernel<<<gg, NTHREADS, SMEM_BYTES>>>(bc, Wf, att2, att_part);

    softmax_kernel<<<BATCH, 256>>>(att_part, bf, alpha);
    pool_kernel<<<dim3(CDIM / 4 / 256, BATCH), 256>>>(conv, alpha, out);
}

// round 13
// speedup vs baseline: 1.1456x; 1.1456x over previous
#include <cuda_runtime.h>
#include <cuda_fp16.h>
#include <math.h>
#include <stdint.h>

// Problem dims (fixed by the reference)
#define BATCH 256
#define NPIX  196
#define CDIM  2048
#define ADIM  512
#define LDIM  512
#define MTOT  (BATCH * NPIX)   // 50176 = 392 * 128

// GEMM tiling (mma.sync m16n8k16, fp16 in / f32 accum, single pass)
#define BM 128
#define BN 128
#define BK 64
#define NBLK (ADIM / BN)       // 4
#define NITER (CDIM / BK)      // 32
#define WM 64
#define WN 32
#define NSTAGE 3

// Scratch (device globals — no allocation allowed)
__device__ float g_att2[BATCH * ADIM];
__device__ float g_att_part[NBLK * MTOT];
__device__ float g_alpha[MTOT];
__device__ __half g_Wc_h[ADIM * CDIM];                 // fp16(Wc)
__device__ __half g_A_h[(size_t)MTOT * CDIM];          // fp16(conv_out)

// smem: row stride 144B (64 fp16 + 16B pad) — conflict-free LDSM
#define ROWB 144
#define TILEB (128 * ROWB)     // 18432
#define SM_A(s) ((s) * (2 * TILEB) + 0)
#define SM_B(s) ((s) * (2 * TILEB) + TILEB)
#define SMEM_BYTES (NSTAGE * 2 * TILEB)   // 110592

__device__ __forceinline__ uint32_t smem_to_u32(const void* p) {
    uint32_t a;
    asm("{ .reg .u64 t; cvta.to.shared.u64 t, %1; cvt.u32.u64 %0, t; }" : "=r"(a) : "l"(p));
    return a;
}
__device__ __forceinline__ void ldsm4(uint32_t* r, uint32_t addr) {
    asm volatile("ldmatrix.sync.aligned.m8n8.x4.shared.b16 {%0,%1,%2,%3}, [%4];"
                 : "=r"(r[0]), "=r"(r[1]), "=r"(r[2]), "=r"(r[3]) : "r"(addr));
}
__device__ __forceinline__ void mma16816(float* c, const uint32_t* a, const uint32_t* b) {
    asm volatile("mma.sync.aligned.m16n8k16.row.col.f32.f16.f16.f32 "
                 "{%0,%1,%2,%3}, {%4,%5,%6,%7}, {%8,%9}, {%0,%1,%2,%3};"
                 : "+f"(c[0]), "+f"(c[1]), "+f"(c[2]), "+f"(c[3])
                 : "r"(a[0]), "r"(a[1]), "r"(a[2]), "r"(a[3]), "r"(b[0]), "r"(b[1]));
}
#define CP_ASYNC16(dst, src) \
    asm volatile("cp.async.cg.shared.global [%0], [%1], 16;" :: "r"(dst), "l"(src))
#define CP_COMMIT() asm volatile("cp.async.commit_group;" ::: "memory")
#define CP_WAIT1()  asm volatile("cp.async.wait_group 1;" ::: "memory")
#define CP_WAIT0()  asm volatile("cp.async.wait_group 0;" ::: "memory")

__device__ __forceinline__ uint32_t pack_h(__half a, __half b) {
    return (uint32_t)__half_as_ushort(a) | ((uint32_t)__half_as_ushort(b) << 16);
}

// ---------------------------------------------------------------------------
// K0a: convert Wc -> fp16
// ---------------------------------------------------------------------------
__global__ void convert_wc_kernel(const float* __restrict__ Wc) {
    const size_t i4 = (size_t)blockIdx.x * 256 + threadIdx.x;
    float4 v = reinterpret_cast<const float4*>(Wc)[i4];
    reinterpret_cast<uint2*>(g_Wc_h)[i4] =
        make_uint2(pack_h(__float2half(v.x), __float2half(v.y)),
                   pack_h(__float2half(v.z), __float2half(v.w)));
}

// ---------------------------------------------------------------------------
// K0b: convert conv_out -> fp16
// ---------------------------------------------------------------------------
__global__ void convert_a_kernel(const float* __restrict__ A) {
    const size_t i4 = (size_t)blockIdx.x * 256 + threadIdx.x;
    float4 v = reinterpret_cast<const float4*>(A)[i4];
    reinterpret_cast<uint2*>(g_A_h)[i4] =
        make_uint2(pack_h(__float2half(v.x), __float2half(v.y)),
                   pack_h(__float2half(v.z), __float2half(v.w)));
}

// ---------------------------------------------------------------------------
// K1: att2[b][a] = lstm[b] . Wl[a] + bl[a]
// ---------------------------------------------------------------------------
__global__ void att2_kernel(const float* __restrict__ lstm,
                            const float* __restrict__ Wl,
                            const float* __restrict__ bl,
                            float* __restrict__ att2) {
    __shared__ float h[8][LDIM];
    const int b0 = blockIdx.x * 8;
    const int a = threadIdx.x;
    #pragma unroll
    for (int i = 0; i < 8; i++) h[i][a] = lstm[(b0 + i) * LDIM + a];
    __syncthreads();
    const float4* w4 = reinterpret_cast<const float4*>(Wl + (size_t)a * LDIM);
    float acc[8] = {0.f, 0.f, 0.f, 0.f, 0.f, 0.f, 0.f, 0.f};
    #pragma unroll 4
    for (int l4 = 0; l4 < LDIM / 4; l4++) {
        float4 wv = w4[l4];
        int l = l4 * 4;
        #pragma unroll
        for (int i = 0; i < 8; i++) {
            acc[i] += h[i][l + 0] * wv.x;
            acc[i] += h[i][l + 1] * wv.y;
            acc[i] += h[i][l + 2] * wv.z;
            acc[i] += h[i][l + 3] * wv.w;
        }
    }
    const float bv = bl[a];
    #pragma unroll
    for (int i = 0; i < 8; i++) att2[(b0 + i) * ADIM + a] = acc[i] + bv;
}

// ---------------------------------------------------------------------------
// K2: fp16 single-pass score GEMM, BK=64, 3-stage cp.async, 2 CTAs/SM.
// Grid (4, 392): bn fast => 4 CTAs share one A tile via L2.
// 256 threads (8 warps 2x4), warp tile 64x32.  (R11 champion config)
// ---------------------------------------------------------------------------
__global__ void __launch_bounds__(256, 2)
score_gemm_kernel(const float* __restrict__ bc,
                  const float* __restrict__ Wf,
                  const float* __restrict__ att2,   // B x 512
                  float* __restrict__ att_part)     // NBLK x M
{
    extern __shared__ char sm[];
    const uint32_t sb = smem_to_u32(sm);
    const int tid = threadIdx.x;
    const int lane = tid & 31;
    const int wid = tid >> 5;
    const int warp_m = wid >> 2;       // 0..1
    const int warp_n = wid & 3;        // 0..3
    const int bn = blockIdx.x;         // 0..3 (fast: A-tile L2 sharing)
    const int bm = blockIdx.y;         // 0..391

    // ldmatrix per-lane offsets (k-quarter kk adds kk*32 bytes)
    uint32_t aoff[4], boff[2];
    {
        const int ar = lane & 15, abyte = (lane >> 4) * 16;
        #pragma unroll
        for (int mb = 0; mb < 4; mb++)
            aoff[mb] = (uint32_t)((warp_m * WM + mb * 16 + ar) * ROWB + abyte);
        const int bnr = (lane & 7) + ((lane >> 4) << 3);
        const int bbyte = ((lane >> 3) & 1) * 16;
        #pragma unroll
        for (int g = 0; g < 2; g++)
            boff[g] = (uint32_t)((warp_n * WN + g * 16 + bnr) * ROWB + bbyte);
    }

    // cp.async: per stage A and B are each 128 rows x 8 chunks(16B) = 1024 chunks
    // -> 4 chunks per thread per matrix
    int c_row[4]; int c_q[4]; uint32_t c_soff[4];
    #pragma unroll
    for (int i = 0; i < 4; i++) {
        const int idx = tid + 256 * i;
        c_row[i] = idx >> 3;
        c_q[i] = idx & 7;
        c_soff[i] = (uint32_t)(c_row[i] * ROWB + c_q[i] * 16);
    }

    float acc[4][4][4];
    #pragma unroll
    for (int mb = 0; mb < 4; mb++)
        #pragma unroll
        for (int nb = 0; nb < 4; nb++)
            #pragma unroll
            for (int j = 0; j < 4; j++) acc[mb][nb][j] = 0.f;

    auto issue = [&](int s) {
        const int buf = s % NSTAGE;
        const int k0 = s * BK;
        #pragma unroll
        for (int i = 0; i < 4; i++) {
            const size_t ag = (size_t)(bm * BM + c_row[i]) * CDIM + k0 + c_q[i] * 8;
            CP_ASYNC16(sb + SM_A(buf) + c_soff[i], (const char*)(g_A_h + ag));
        }
        #pragma unroll
        for (int i = 0; i < 4; i++) {
            const size_t bg = (size_t)(bn * BN + c_row[i]) * CDIM + k0 + c_q[i] * 8;
            CP_ASYNC16(sb + SM_B(buf) + c_soff[i], (const char*)(g_Wc_h + bg));
        }
        CP_COMMIT();
    };

    issue(0); issue(1);
    CP_WAIT1();            // stage 0 complete
    __syncthreads();

    #pragma unroll 1
    for (int it = 0; it < NITER; it++) {
        const int buf = it % NSTAGE;
        const bool more = (it + 2 < NITER);

        // kk = 0 first: start LDSM immediately after the barrier
        {
            uint32_t a[4][4], b[2][4];
            #pragma unroll
            for (int g = 0; g < 2; g++) ldsm4(b[g], sb + SM_B(buf) + boff[g]);
            #pragma unroll
            for (int mb = 0; mb < 4; mb++) ldsm4(a[mb], sb + SM_A(buf) + aoff[mb]);
            #pragma unroll
            for (int mb = 0; mb < 4; mb++)
                #pragma unroll
                for (int nb = 0; nb < 4; nb++)
                    mma16816(acc[mb][nb], a[mb], &b[nb >> 1][(nb & 1) * 2]);
        }

        if (more) issue(it + 2);   // global fetch for it+2 (>= 1 stage of slack)

        #pragma unroll
        for (int kk = 1; kk < 4; kk++) {
            uint32_t a[4][4], b[2][4];
            #pragma unroll
            for (int g = 0; g < 2; g++) ldsm4(b[g], sb + SM_B(buf) + boff[g] + kk * 32);
            #pragma unroll
            for (int mb = 0; mb < 4; mb++) ldsm4(a[mb], sb + SM_A(buf) + aoff[mb] + kk * 32);
            #pragma unroll
            for (int mb = 0; mb < 4; mb++)
                #pragma unroll
                for (int nb = 0; nb < 4; nb++)
                    mma16816(acc[mb][nb], a[mb], &b[nb >> 1][(nb & 1) * 2]);
        }

        if (more) { CP_WAIT1(); } else { CP_WAIT0(); }
        __syncthreads();
    }

    // ---- epilogue: relu(C + bc + att2) . Wf reduced over n ----
    float wfv[8], bcv[8];
    const int ncol0 = bn * BN + warp_n * WN;
    #pragma unroll
    for (int nb = 0; nb < 4; nb++)
        #pragma unroll
        for (int jj = 0; jj < 2; jj++) {
            const int n = ncol0 + nb * 8 + 2 * (lane & 3) + jj;
            wfv[nb * 2 + jj] = Wf[n];
            bcv[nb * 2 + jj] = bc[n];
        }

    float* red = reinterpret_cast<float*>(sm);   // [4][128]
    #pragma unroll
    for (int mb = 0; mb < 4; mb++) {
        #pragma unroll
        for (int half = 0; half < 2; half++) {
            const int m_loc = warp_m * WM + mb * 16 + (lane >> 2) + half * 8;
            const int m = bm * BM + m_loc;
            const int b = m / NPIX;
            const float* a2 = att2 + (size_t)b * ADIM + ncol0;
            float s = 0.f;
            #pragma unroll
            for (int nb = 0; nb < 4; nb++)
                #pragma unroll
                for (int jj = 0; jj < 2; jj++) {
                    const int ci = half * 2 + jj;
                    const int nrel = nb * 8 + 2 * (lane & 3) + jj;
                    float v = acc[mb][nb][ci] + bcv[nb * 2 + jj] + a2[nrel];
                    s += fmaxf(v, 0.f) * wfv[nb * 2 + jj];
                }
            s += __shfl_xor_sync(0xFFFFFFFF, s, 1);
            s += __shfl_xor_sync(0xFFFFFFFF, s, 2);
            if ((lane & 3) == 0) red[warp_n * BM + m_loc] = s;
        }
    }
    __syncthreads();
    if (tid < BM) {
        float s = red[0 * BM + tid] + red[1 * BM + tid] + red[2 * BM + tid] + red[3 * BM + tid];
        att_part[(size_t)bn * MTOT + bm * BM + tid] = s;
    }
}

// ---------------------------------------------------------------------------
// K3: softmax over P=196 per batch row (4 partials).
// ---------------------------------------------------------------------------
__global__ void softmax_kernel(const float* __restrict__ att_part,
                               const float* __restrict__ bf,
                               float* __restrict__ alpha) {
    __shared__ float sv[256];
    const int b = blockIdx.x;
    const int tid = threadIdx.x;
    float val = 0.f;
    float v = -INFINITY;
    if (tid < NPIX) {
        const int m = b * NPIX + tid;
        val = bf[0] + att_part[0 * MTOT + m] + att_part[1 * MTOT + m]
            + att_part[2 * MTOT + m] + att_part[3 * MTOT + m];
        v = val;
    }
    sv[tid] = v;
    __syncthreads();
    #pragma unroll
    for (int s = 128; s > 0; s >>= 1) {
        if (tid < s) sv[tid] = fmaxf(sv[tid], sv[tid + s]);
        __syncthreads();
    }
    const float mx = sv[0];
    __syncthreads();
    const float e = (tid < NPIX) ? expf(val - mx) : 0.f;
    sv[tid] = e;
    __syncthreads();
    #pragma unroll
    for (int s = 128; s > 0; s >>= 1) {
        if (tid < s) sv[tid] = sv[tid] + sv[tid + s];
        __syncthreads();
    }
    const float sum = sv[0];
    if (tid < NPIX) alpha[b * NPIX + tid] = e / sum;
}

// ---------------------------------------------------------------------------
// K4: out[b][c] = sum_p A_h[b][p][c] * alpha[b][p]   (fp16 reads, half traffic)
// thread covers 4 channels (uint2 = 4 halfs); grid (CDIM/4/256 = 2, BATCH)
// ---------------------------------------------------------------------------
__global__ void pool_kernel(const float* __restrict__ alpha,
                            float* __restrict__ out) {
    __shared__ float al[NPIX];
    const int b = blockIdx.y;
    const int c4 = blockIdx.x * 256 + threadIdx.x;   // 0..511
    if (threadIdx.x < NPIX) al[threadIdx.x] = alpha[b * NPIX + threadIdx.x];
    __syncthreads();
    const uint2* cp = reinterpret_cast<const uint2*>(g_A_h + (size_t)b * NPIX * CDIM) + c4;
    float4 a0 = make_float4(0.f, 0.f, 0.f, 0.f);
    float4 a1 = make_float4(0.f, 0.f, 0.f, 0.f);
    #pragma unroll 4
    for (int p = 0; p < NPIX; p += 2) {
        uint2 u0 = cp[(size_t)p * (CDIM / 4)];
        uint2 u1 = cp[(size_t)(p + 1) * (CDIM / 4)];
        float w0 = al[p], w1 = al[p + 1];
        float2 x0 = __half22float2(*reinterpret_cast<__half2*>(&u0.x));
        float2 y0 = __half22float2(*reinterpret_cast<__half2*>(&u0.y));
        float2 x1 = __half22float2(*reinterpret_cast<__half2*>(&u1.x));
        float2 y1 = __half22float2(*reinterpret_cast<__half2*>(&u1.y));
        a0.x += x0.x * w0; a0.y += x0.y * w0; a0.z += y0.x * w0; a0.w += y0.y * w0;
        a1.x += x1.x * w1; a1.y += x1.y * w1; a1.z += y1.x * w1; a1.w += y1.y * w1;
    }
    float4 r = make_float4(a0.x + a1.x, a0.y + a1.y, a0.z + a1.z, a0.w + a1.w);
    reinterpret_cast<float4*>(out)[(size_t)b * (CDIM / 4) + c4] = r;
}

// ---------------------------------------------------------------------------
extern "C" void kernel_launch(void* const* d_in, const int* in_sizes, int n_in,
                              void* d_out, int out_size) {
    const float* conv = (const float*)d_in[0];
    const float* lstm = (const float*)d_in[1];
    const float* Wc   = (const float*)d_in[2];
    const float* bc   = (const float*)d_in[3];
    const float* Wl   = (const float*)d_in[4];
    const float* bl   = (const float*)d_in[5];
    const float* Wf   = (const float*)d_in[6];
    const float* bf   = (const float*)d_in[7];
    float* out = (float*)d_out;

    float* att2;     cudaGetSymbolAddress((void**)&att2, g_att2);
    float* att_part; cudaGetSymbolAddress((void**)&att_part, g_att_part);
    float* alpha;    cudaGetSymbolAddress((void**)&alpha, g_alpha);

    cudaFuncSetAttribute(score_gemm_kernel,
                         cudaFuncAttributeMaxDynamicSharedMemorySize, SMEM_BYTES);

    convert_wc_kernel<<<(ADIM * CDIM / 4) / 256, 256>>>(Wc);
    convert_a_kernel<<<(int)(((size_t)MTOT * CDIM / 4) / 256), 256>>>(conv);
    att2_kernel<<<BATCH / 8, LDIM>>>(lstm, Wl, bl, att2);

    dim3 gg(NBLK, MTOT / BM);
    score_gemm_kernel<<<gg, 256, SMEM_BYTES>>>(bc, Wf, att2, att_part);

    softmax_kernel<<<BATCH, 256>>>(att_part, bf, alpha);
    pool_kernel<<<dim3(CDIM / 4 / 256, BATCH), 256>>>(alpha, out);
}